// round 10
// baseline (speedup 1.0000x reference)
#include <cuda_runtime.h>

// Fixed problem shapes.
#define Bb      8
#define CF      256
#define Hh      128
#define Ww      128
#define HL      512
#define WL      512
#define C_OLD   16
#define HW      (Hh * Ww)                 // 16384
#define NPIX    (Bb * HW)                 // 131072
#define NBLK    (NPIX / 256)              // 512 blocks, 256 pixels each
#define NTHR    256

// Persistent scratch (no allocation). Zero at module load; the last-block
// ticket resets everything dirtied, so each graph replay starts identical.
__device__ int   g_done = 0;
__device__ float g_sum[16];
__device__ int   g_cnt[16];

__global__ void __launch_bounds__(NTHR)
k_all(const int* __restrict__ labels,
      const float* __restrict__ outputs_old,
      const float* __restrict__ features,
      const float* __restrict__ proto,
      const int* __restrict__ classes_old,
      const int* __restrict__ inc_step,
      float* __restrict__ out)
{
    const int tid  = threadIdx.x;
    const int lane = tid & 31;
    const int wid  = tid >> 5;            // 8 warps = 8 pixel groups of 32

    __shared__ float s_proto[16 * 257];   // padded rows; classes 0..15 reachable
    __shared__ float s_sum[16];
    __shared__ int   s_cnt[16];
    __shared__ unsigned char s_id[256];   // per-pixel pseudo-class (block-local)

    if (tid < 16) { s_sum[tid] = 0.0f; s_cnt[tid] = 0; }
    // stage prototypes (classes 0..15, vectorized)
    for (int i = tid; i < 16 * (CF / 4); i += NTHR) {
        int row = i >> 6, col4 = (i & 63) << 2;
        float4 v = reinterpret_cast<const float4*>(proto)[i];
        float* dst = s_proto + row * 257 + col4;
        dst[0] = v.x; dst[1] = v.y; dst[2] = v.z; dst[3] = v.w;
    }

    // ---- Phase 1: label gather + conditional 16-ch argmax (one pixel/thread) ----
    const int pix0 = blockIdx.x * 256;    // 256-aligned -> single b, aligned groups
    const int pix  = pix0 + tid;
    const int b    = pix >> 14;
    const int h    = (pix >> 7) & 127;
    const int w    = pix & 127;

    int lab = labels[(b * HL + 4 * h) * WL + 4 * w];   // nearest-down: src = 4*dst
    int id = 0;
    if (lab == 0) {
        const float* p = outputs_old
                       + (size_t)b * C_OLD * HL * WL
                       + (size_t)(4 * h) * WL + 4 * w;
        float best = p[0];
        #pragma unroll
        for (int c = 1; c < C_OLD; ++c) {
            float v = p[(size_t)c * HL * WL];
            if (v > best) { best = v; id = c; }        // strict > = first-max (jnp.argmax)
        }
    }
    s_id[tid] = (unsigned char)id;
    if (id) atomicAdd(&s_cnt[id], 1);
    __syncthreads();

    // ---- Phase 2: warp per 32-pixel group (one 128B line per channel) ----
    // lane = pixel; 256 fully-coalesced 128B streaming loads per occupied
    // group; each lane accumulates its own pixel's 256-channel MSE.
    {
        int myid = s_id[tid];             // == s_id[(wid<<5) | lane]
        unsigned act = __ballot_sync(0xffffffffu, myid != 0);
        if (act) {
            const float* fb = features + (size_t)b * (CF * HW) + (pix0 & 16383) + tid;
            const float* pp = s_proto + myid * 257;    // distinct ids -> distinct banks
            float acc = 0.0f;
            #pragma unroll 8
            for (int c = 0; c < CF; ++c) {
                float d = __ldcs(&fb[c * HW]) - pp[c];
                acc = fmaf(d, d, acc);
            }
            if (myid)
                atomicAdd(&s_sum[myid], acc * (1.0f / CF));
        }
    }
    __syncthreads();

    // ---- Flush block totals ----
    if (tid < 16) {
        if (s_cnt[tid])          atomicAdd(&g_cnt[tid], s_cnt[tid]);
        if (s_sum[tid] != 0.0f)  atomicAdd(&g_sum[tid], s_sum[tid]);
    }

    // ---- Non-spinning last-block ticket: finalize + scratch reset ----
    __threadfence();
    __syncthreads();
    __shared__ int s_ticket;
    if (tid == 0) s_ticket = atomicAdd(&g_done, 1);
    __syncthreads();
    if (s_ticket == NBLK - 1) {
        __threadfence();                  // all blocks' atomics now visible
        if (tid < 32) {
            int nc = *classes_old;
            if (nc > 16) nc = 16;
            float v = 0.0f;
            if (lane >= 1 && lane < nc && g_cnt[lane] > 0)
                v = g_sum[lane] / (float)g_cnt[lane];
            #pragma unroll
            for (int o = 16; o; o >>= 1)
                v += __shfl_xor_sync(0xffffffffu, v, o);
            if (lane == 0)
                out[0] = (*inc_step == 0) ? 0.0f : v;
        }
        __syncthreads();
        if (tid == 0) g_done = 0;
        if (tid < 16) { g_sum[tid] = 0.0f; g_cnt[tid] = 0; }
        __threadfence();
    }
}

extern "C" void kernel_launch(void* const* d_in, const int* in_sizes, int n_in,
                              void* d_out, int out_size) {
    // 0: outputs (unused)  1: outputs_old f32 [8,16,512,512]
    // 2: features f32 [8,256,128,128]  3: features_old (unused)
    // 4: labels i32 [8,512,512]  5: prototypes f32 [21,256]
    // 6: classes_old i32  7: incremental_step i32
    const float* outputs_old = (const float*)d_in[1];
    const float* features    = (const float*)d_in[2];
    const int*   labels      = (const int*)  d_in[4];
    const float* prototypes  = (const float*)d_in[5];
    const int*   classes_old = (const int*)  d_in[6];
    const int*   inc_step    = (const int*)  d_in[7];

    k_all<<<NBLK, NTHR>>>(labels, outputs_old, features, prototypes,
                          classes_old, inc_step, (float*)d_out);
}

// round 13
// speedup vs baseline: 1.4182x; 1.4182x over previous
#include <cuda_runtime.h>

// Fixed problem shapes.
#define Bb      8
#define CF      256
#define Hh      128
#define Ww      128
#define HL      512
#define WL      512
#define C_OLD   16
#define HW      (Hh * Ww)                 // 16384
#define NPIX    (Bb * HW)                 // 131072
#define NBLK    (NPIX / 256)              // 512 blocks, 256 pixels each
#define NTHR    256
#define FULLM   0xffffffffu

// Persistent scratch (no allocation). Zero at module load; the last-block
// ticket resets everything dirtied, so each graph replay starts identical.
__device__ int   g_done = 0;
__device__ float g_sum[16];
__device__ int   g_cnt[16];

__global__ void __launch_bounds__(NTHR)
k_all(const int* __restrict__ labels,
      const float* __restrict__ outputs_old,
      const float* __restrict__ features,
      const float* __restrict__ proto,
      const int* __restrict__ classes_old,
      const int* __restrict__ inc_step,
      float* __restrict__ out)
{
    const int tid  = threadIdx.x;
    const int lane = tid & 31;
    const int wid  = tid >> 5;            // 8 warps = 8 x 32-pixel line groups

    __shared__ float s_proto[16 * 257];   // padded rows; classes 0..15 reachable
    __shared__ float s_sum[16];
    __shared__ int   s_cnt[16];

    if (tid < 16) { s_sum[tid] = 0.0f; s_cnt[tid] = 0; }
    for (int i = tid; i < 16 * (CF / 4); i += NTHR) {
        int row = i >> 6, col4 = (i & 63) << 2;
        float4 v = reinterpret_cast<const float4*>(proto)[i];
        float* dst = s_proto + row * 257 + col4;
        dst[0] = v.x; dst[1] = v.y; dst[2] = v.z; dst[3] = v.w;
    }
    __syncthreads();   // s_sum/s_cnt/s_proto ready before any warp uses them

    // ---- Phase 1: label gather + conditional 16-ch argmax (one pixel/thread) ----
    const int pix0 = blockIdx.x * 256;    // 256-aligned -> single b, aligned groups
    const int pix  = pix0 + tid;
    const int b    = pix >> 14;
    const int h    = (pix >> 7) & 127;
    const int w    = pix & 127;

    int lab = labels[(b * HL + 4 * h) * WL + 4 * w];   // nearest-down: src = 4*dst
    int id = 0;
    if (lab == 0) {
        const float* p = outputs_old
                       + (size_t)b * C_OLD * HL * WL
                       + (size_t)(4 * h) * WL + 4 * w;
        float best = p[0];
        #pragma unroll
        for (int c = 1; c < C_OLD; ++c) {
            float v = p[(size_t)c * HL * WL];
            if (v > best) { best = v; id = c; }        // strict > = first-max (jnp.argmax)
        }
    }
    if (id) atomicAdd(&s_cnt[id], 1);

    // ---- Phase 2: warp sweeps active pixels of ITS OWN 32-pixel group ----
    // lane = channel stripe: each LDG touches 32 distinct 128B lines -> 32
    // line-requests in flight per instruction (high MLP). Two pixels per
    // iteration double in-flight lines and share one reduce chain.
    {
        unsigned mask = __ballot_sync(FULLM, id != 0);
        const float* fb = features + (size_t)b * (CF * HW) + (pix0 & 16383) + (wid << 5);
        while (mask) {
            int j0 = __ffs(mask) - 1; mask &= mask - 1;
            int j1 = 0, has1 = 0;
            if (mask) { j1 = __ffs(mask) - 1; mask &= mask - 1; has1 = 1; }

            int id0 = __shfl_sync(FULLM, id, j0);
            int id1 = __shfl_sync(FULLM, id, j1);
            const float* p0 = s_proto + id0 * 257;
            const float* p1 = s_proto + id1 * 257;

            float a0 = 0.0f, a1 = 0.0f;
            #pragma unroll
            for (int k = 0; k < CF / 32; ++k) {
                int c = lane + 32 * k;
                float f0 = fb[c * HW + j0];
                float f1 = has1 ? fb[c * HW + j1] : 0.0f;
                float d0 = f0 - p0[c];
                float d1 = has1 ? (f1 - p1[c]) : 0.0f;
                a0 = fmaf(d0, d0, a0);
                a1 = fmaf(d1, d1, a1);
            }
            #pragma unroll
            for (int o = 16; o; o >>= 1) {
                a0 += __shfl_xor_sync(FULLM, a0, o);
                a1 += __shfl_xor_sync(FULLM, a1, o);
            }
            if (lane == 0) {
                atomicAdd(&s_sum[id0], a0 * (1.0f / CF));
                if (has1) atomicAdd(&s_sum[id1], a1 * (1.0f / CF));
            }
        }
    }
    __syncthreads();

    // ---- Flush block totals ----
    if (tid < 16) {
        if (s_cnt[tid])          atomicAdd(&g_cnt[tid], s_cnt[tid]);
        if (s_sum[tid] != 0.0f)  atomicAdd(&g_sum[tid], s_sum[tid]);
    }

    // ---- Non-spinning last-block ticket: finalize + scratch reset ----
    __threadfence();
    __syncthreads();
    __shared__ int s_ticket;
    if (tid == 0) s_ticket = atomicAdd(&g_done, 1);
    __syncthreads();
    if (s_ticket == NBLK - 1) {
        __threadfence();                  // all blocks' atomics now visible
        if (tid < 32) {
            int nc = *classes_old;
            if (nc > 16) nc = 16;
            float v = 0.0f;
            if (lane >= 1 && lane < nc && g_cnt[lane] > 0)
                v = g_sum[lane] / (float)g_cnt[lane];
            #pragma unroll
            for (int o = 16; o; o >>= 1)
                v += __shfl_xor_sync(FULLM, v, o);
            if (lane == 0)
                out[0] = (*inc_step == 0) ? 0.0f : v;
        }
        __syncthreads();
        if (tid == 0) g_done = 0;
        if (tid < 16) { g_sum[tid] = 0.0f; g_cnt[tid] = 0; }
        __threadfence();
    }
}

extern "C" void kernel_launch(void* const* d_in, const int* in_sizes, int n_in,
                              void* d_out, int out_size) {
    // 0: outputs (unused)  1: outputs_old f32 [8,16,512,512]
    // 2: features f32 [8,256,128,128]  3: features_old (unused)
    // 4: labels i32 [8,512,512]  5: prototypes f32 [21,256]
    // 6: classes_old i32  7: incremental_step i32
    const float* outputs_old = (const float*)d_in[1];
    const float* features    = (const float*)d_in[2];
    const int*   labels      = (const int*)  d_in[4];
    const float* prototypes  = (const float*)d_in[5];
    const int*   classes_old = (const int*)  d_in[6];
    const int*   inc_step    = (const int*)  d_in[7];

    k_all<<<NBLK, NTHR>>>(labels, outputs_old, features, prototypes,
                          classes_old, inc_step, (float*)d_out);
}